// round 11
// baseline (speedup 1.0000x reference)
#include <cuda_runtime.h>
#include <cuda_bf16.h>
#include <cstdint>
#include <math_constants.h>

// Problem constants
#define BSZ 4
#define SEQ 1024
#define TOK (BSZ * SEQ)          // 4096
#define DMODEL 2048
#define NHEADS 32
#define NKV 8
#define HDIM 64
#define GROUPS (NHEADS / NKV)     // 4
#define KVDIM (NKV * HDIM)        // 512
#define QKVN (DMODEL + 2 * KVDIM) // 3072
#define ATTN_SCALE 0.125f

// ---------------- scratch (static device globals; no allocation) ----------
__device__ __align__(16) __nv_bfloat16 g_Ahi[(size_t)TOK * DMODEL];
__device__ __align__(16) __nv_bfloat16 g_Alo[(size_t)TOK * DMODEL];
__device__ __align__(16) __nv_bfloat16 g_Bhi[(size_t)QKVN * DMODEL]; // [N,K]
__device__ __align__(16) __nv_bfloat16 g_Blo[(size_t)QKVN * DMODEL];
__device__ __align__(16) __nv_bfloat16 g_Qh[(size_t)TOK * DMODEL];
__device__ __align__(16) __nv_bfloat16 g_Ql[(size_t)TOK * DMODEL];
__device__ __align__(16) __nv_bfloat16 g_Kh[(size_t)TOK * KVDIM];
__device__ __align__(16) __nv_bfloat16 g_Kl[(size_t)TOK * KVDIM];
__device__ __align__(16) __nv_bfloat16 g_Vh[(size_t)TOK * KVDIM];
__device__ __align__(16) __nv_bfloat16 g_Vl[(size_t)TOK * KVDIM];

// =================== PTX helpers (compute_103-safe) =========================
__device__ __forceinline__ uint32_t smem_u32(const void* p) {
    uint32_t a;
    asm("{ .reg .u64 t; cvta.to.shared.u64 t, %1; cvt.u32.u64 %0, t; }"
        : "=r"(a) : "l"(p));
    return a;
}

#define CP_ASYNC16(dst, src) \
    asm volatile("cp.async.cg.shared.global [%0], [%1], 16;" \
                 :: "r"(dst), "l"(src) : "memory")
#define CP_COMMIT() asm volatile("cp.async.commit_group;" ::: "memory")
#define CP_WAIT1()  asm volatile("cp.async.wait_group 1;" ::: "memory")
#define CP_WAIT0()  asm volatile("cp.async.wait_group 0;" ::: "memory")

#define LDMATRIX_X4(r0, r1, r2, r3, addr) \
    asm volatile("ldmatrix.sync.aligned.m8n8.x4.shared.b16 {%0,%1,%2,%3}, [%4];" \
                 : "=r"(r0), "=r"(r1), "=r"(r2), "=r"(r3) : "r"(addr))

#define LDMATRIX_X4T(r0, r1, r2, r3, addr) \
    asm volatile("ldmatrix.sync.aligned.m8n8.x4.trans.shared.b16 {%0,%1,%2,%3}, [%4];" \
                 : "=r"(r0), "=r"(r1), "=r"(r2), "=r"(r3) : "r"(addr))

#define MMA16816(d, a, b) \
    asm volatile("mma.sync.aligned.m16n8k16.row.col.f32.bf16.bf16.f32 " \
                 "{%0,%1,%2,%3}, {%4,%5,%6,%7}, {%8,%9}, {%0,%1,%2,%3};" \
                 : "+f"((d)[0]), "+f"((d)[1]), "+f"((d)[2]), "+f"((d)[3]) \
                 : "r"((a)[0]), "r"((a)[1]), "r"((a)[2]), "r"((a)[3]), \
                   "r"((b)[0]), "r"((b)[1]))

// 128-byte rows, 8-chunk swizzle
__device__ __forceinline__ uint32_t swz8(int row, int c16) {
    return (uint32_t)(row * 128 + ((c16 ^ (row & 7)) * 16));
}

// =================== conversion kernels =====================================
__global__ void split_kernel(const float* __restrict__ A,
                             __nv_bfloat162* __restrict__ H,
                             __nv_bfloat162* __restrict__ L, int n4)
{
    int i = blockIdx.x * blockDim.x + threadIdx.x;
    if (i >= n4) return;
    float4 v = reinterpret_cast<const float4*>(A)[i];
    __nv_bfloat16 h0 = __float2bfloat16(v.x);
    __nv_bfloat16 h1 = __float2bfloat16(v.y);
    __nv_bfloat16 h2 = __float2bfloat16(v.z);
    __nv_bfloat16 h3 = __float2bfloat16(v.w);
    __nv_bfloat16 l0 = __float2bfloat16(v.x - __bfloat162float(h0));
    __nv_bfloat16 l1 = __float2bfloat16(v.y - __bfloat162float(h1));
    __nv_bfloat16 l2 = __float2bfloat16(v.z - __bfloat162float(h2));
    __nv_bfloat16 l3 = __float2bfloat16(v.w - __bfloat162float(h3));
    H[2 * i]     = __nv_bfloat162(h0, h1);
    H[2 * i + 1] = __nv_bfloat162(h2, h3);
    L[2 * i]     = __nv_bfloat162(l0, l1);
    L[2 * i + 1] = __nv_bfloat162(l2, l3);
}

__global__ void transpose_split(const float* __restrict__ W,
                                __nv_bfloat16* __restrict__ Th,
                                __nv_bfloat16* __restrict__ Tl, int N, int rowoff)
{
    __shared__ float tile[32][33];
    int n = blockIdx.x * 32 + threadIdx.x;
    int k = blockIdx.y * 32 + threadIdx.y;
#pragma unroll
    for (int j = 0; j < 32; j += 8)
        tile[threadIdx.y + j][threadIdx.x] = W[(size_t)(k + j) * N + n];
    __syncthreads();
    int k2 = blockIdx.y * 32 + threadIdx.x;
    int n2 = blockIdx.x * 32 + threadIdx.y + rowoff;
#pragma unroll
    for (int j = 0; j < 32; j += 8) {
        float v = tile[threadIdx.x][threadIdx.y + j];
        __nv_bfloat16 h = __float2bfloat16(v);
        Th[(size_t)(n2 + j) * DMODEL + k2] = h;
        Tl[(size_t)(n2 + j) * DMODEL + k2] =
            __float2bfloat16(v - __bfloat162float(h));
    }
}

// =================== HMMA GEMM: BK=64, 3-stage (verified R8 mainloop) =======
// EPI=0: write fp32 C. EPI=1: fused rope/scale/bf16-split epilogue (QKV).
#define BM 128
#define BN 128
#define BK 64
#define TILE_B (128 * BK * 2)          // 16384
#define STAGE_B (4 * TILE_B)           // 65536
#define GEMM_SMEM (3 * STAGE_B)        // 196608

__device__ __forceinline__ void stage_load(
    const __nv_bfloat16* __restrict__ aH, const __nv_bfloat16* __restrict__ aL,
    const __nv_bfloat16* __restrict__ bH, const __nv_bfloat16* __restrict__ bL,
    uint32_t sbase, int k0, int tid)
{
#pragma unroll
    for (int j = 0; j < 4; j++) {
        int i = tid + j * 256;
        int row = i >> 3;
        int c16 = i & 7;
        uint32_t doff = swz8(row, c16);
        size_t goff = (size_t)row * DMODEL + k0 + c16 * 8;
        CP_ASYNC16(sbase + 0 * TILE_B + doff, aH + goff);
        CP_ASYNC16(sbase + 1 * TILE_B + doff, aL + goff);
        CP_ASYNC16(sbase + 2 * TILE_B + doff, bH + goff);
        CP_ASYNC16(sbase + 3 * TILE_B + doff, bL + goff);
    }
}

template <int EPI>
__global__ void __launch_bounds__(256, 1) gemm_mma(
    const __nv_bfloat16* __restrict__ Ahi, const __nv_bfloat16* __restrict__ Alo,
    const __nv_bfloat16* __restrict__ Bhi, const __nv_bfloat16* __restrict__ Blo,
    float* __restrict__ C, int N,
    const float* __restrict__ cs, const float* __restrict__ sn,
    __nv_bfloat16* __restrict__ Qh, __nv_bfloat16* __restrict__ Ql,
    __nv_bfloat16* __restrict__ Kh, __nv_bfloat16* __restrict__ Kl,
    __nv_bfloat16* __restrict__ Vh, __nv_bfloat16* __restrict__ Vl)
{
    extern __shared__ char smem[];
    uint32_t sb = smem_u32(smem);
    const int tid = threadIdx.x;
    const int lane = tid & 31;
    const int wid = tid >> 5;
    const int wm = wid >> 2;
    const int wn = wid & 3;
    const int brow = blockIdx.y * BM;
    const int bcol = blockIdx.x * BN;

    const __nv_bfloat16* aH = Ahi + (size_t)brow * DMODEL;
    const __nv_bfloat16* aL = Alo + (size_t)brow * DMODEL;
    const __nv_bfloat16* bH = Bhi + (size_t)bcol * DMODEL;
    const __nv_bfloat16* bL = Blo + (size_t)bcol * DMODEL;

    float acc[4][4][4];
#pragma unroll
    for (int i = 0; i < 4; i++)
#pragma unroll
        for (int j = 0; j < 4; j++)
#pragma unroll
            for (int q = 0; q < 4; q++) acc[i][j][q] = 0.f;

    const int NC = DMODEL / BK;   // 32
#pragma unroll
    for (int s = 0; s < 3; s++) {
        stage_load(aH, aL, bH, bL, sb + s * STAGE_B, s * BK, tid);
        CP_COMMIT();
    }

    for (int c = 0; c < NC; c++) {
        if (c + 2 < NC)      asm volatile("cp.async.wait_group 2;" ::: "memory");
        else if (c + 1 < NC) CP_WAIT1();
        else                 CP_WAIT0();
        __syncthreads();

        uint32_t st = sb + (uint32_t)(c % 3) * STAGE_B;

#pragma unroll
        for (int ks = 0; ks < 4; ks++) {
            uint32_t fAh[4][4], fAl[4][4];
#pragma unroll
            for (int mt = 0; mt < 4; mt++) {
                int row = wm * 64 + mt * 16 + (lane & 15);
                int c16 = ks * 2 + (lane >> 4);
                uint32_t off = swz8(row, c16);
                LDMATRIX_X4(fAh[mt][0], fAh[mt][1], fAh[mt][2], fAh[mt][3],
                            st + 0 * TILE_B + off);
                LDMATRIX_X4(fAl[mt][0], fAl[mt][1], fAl[mt][2], fAl[mt][3],
                            st + 1 * TILE_B + off);
            }
            uint32_t fBh[4][2], fBl[4][2];
#pragma unroll
            for (int pr = 0; pr < 2; pr++) {
                int nrel = wn * 32 + pr * 16 + ((lane >> 4) * 8 + (lane & 7));
                int c16 = ks * 2 + ((lane >> 3) & 1);
                uint32_t off = swz8(nrel, c16);
                LDMATRIX_X4(fBh[2 * pr][0], fBh[2 * pr][1],
                            fBh[2 * pr + 1][0], fBh[2 * pr + 1][1],
                            st + 2 * TILE_B + off);
                LDMATRIX_X4(fBl[2 * pr][0], fBl[2 * pr][1],
                            fBl[2 * pr + 1][0], fBl[2 * pr + 1][1],
                            st + 3 * TILE_B + off);
            }
#pragma unroll
            for (int mt = 0; mt < 4; mt++)
#pragma unroll
                for (int nt = 0; nt < 4; nt++) {
                    MMA16816(acc[mt][nt], fAh[mt], fBh[nt]);
                    MMA16816(acc[mt][nt], fAh[mt], fBl[nt]);
                    MMA16816(acc[mt][nt], fAl[mt], fBh[nt]);
                }
        }
        __syncthreads();
        if (c + 3 < NC) {
            stage_load(aH, aL, bH, bL, st, (c + 3) * BK, tid);
            CP_COMMIT();
        }
    }

    if (EPI == 0) {
#pragma unroll
        for (int mt = 0; mt < 4; mt++) {
#pragma unroll
            for (int nt = 0; nt < 4; nt++) {
                int m = brow + wm * 64 + mt * 16 + (lane >> 2);
                int n = bcol + wn * 32 + nt * 8 + (lane & 3) * 2;
                float2 v0 = make_float2(acc[mt][nt][0], acc[mt][nt][1]);
                float2 v1 = make_float2(acc[mt][nt][2], acc[mt][nt][3]);
                *reinterpret_cast<float2*>(C + (size_t)m * N + n) = v0;
                *reinterpret_cast<float2*>(C + (size_t)(m + 8) * N + n) = v1;
            }
        }
    } else {
        // fused rope + scale + bf16 hi/lo split epilogue
        __syncthreads();                      // all warps done reading SMEM
        float* stile = reinterpret_cast<float*>(smem);
        const int TS = 132;                   // padded row stride (floats)
#pragma unroll
        for (int mt = 0; mt < 4; mt++) {
#pragma unroll
            for (int nt = 0; nt < 4; nt++) {
                int ml = wm * 64 + mt * 16 + (lane >> 2);
                int nl = wn * 32 + nt * 8 + (lane & 3) * 2;
                stile[ml * TS + nl]           = acc[mt][nt][0];
                stile[ml * TS + nl + 1]       = acc[mt][nt][1];
                stile[(ml + 8) * TS + nl]     = acc[mt][nt][2];
                stile[(ml + 8) * TS + nl + 1] = acc[mt][nt][3];
            }
        }
        __syncthreads();

        if (bcol < DMODEL + KVDIM) {
            // Q or K section: rope pairs (i, i+32) within each 64-wide head
            const bool isQ = (bcol < DMODEL);
            const float scale = isQ ? ATTN_SCALE : 1.0f;
            __nv_bfloat16* Xh = isQ ? Qh : Kh;
            __nv_bfloat16* Xl = isQ ? Ql : Kl;
            const int stride  = isQ ? DMODEL : KVDIM;
            const int cb      = isQ ? bcol : bcol - DMODEL;
            for (int p = tid; p < 128 * 64; p += 256) {
                int r  = p >> 6;
                int hl = (p >> 5) & 1;
                int i  = p & 31;
                int t  = brow + r;
                float c = cs[t * 32 + i];
                float s = sn[t * 32 + i];
                float x1 = stile[r * TS + hl * 64 + i];
                float x2 = stile[r * TS + hl * 64 + i + 32];
                float y1 = (x1 * c - x2 * s) * scale;
                float y2 = (x2 * c + x1 * s) * scale;
                __nv_bfloat16 h1 = __float2bfloat16(y1);
                __nv_bfloat16 h2 = __float2bfloat16(y2);
                size_t o = (size_t)t * stride + cb + hl * 64 + i;
                Xh[o]      = h1;
                Xh[o + 32] = h2;
                Xl[o]      = __float2bfloat16(y1 - __bfloat162float(h1));
                Xl[o + 32] = __float2bfloat16(y2 - __bfloat162float(h2));
            }
        } else {
            // V section: plain hi/lo split
            const int cb = bcol - DMODEL - KVDIM;
            for (int p = tid; p < 128 * 128; p += 256) {
                int r = p >> 7;
                int n = p & 127;
                int t = brow + r;
                float v = stile[r * TS + n];
                __nv_bfloat16 h = __float2bfloat16(v);
                size_t o = (size_t)t * KVDIM + cb + n;
                Vh[o] = h;
                Vl[o] = __float2bfloat16(v - __bfloat162float(h));
            }
        }
    }
}

// =================== tensor-core flash attention (verified R8) ==============
#define FQ_SMEM 32768
#define KV_BUF  32768
#define FLASH_SMEM (FQ_SMEM + 2 * KV_BUF)

__device__ __forceinline__ void stage_kv(
    const __nv_bfloat16* __restrict__ Kh, const __nv_bfloat16* __restrict__ Kl,
    const __nv_bfloat16* __restrict__ Vh, const __nv_bfloat16* __restrict__ Vl,
    uint32_t sbase, size_t gbase, int tid)
{
#pragma unroll
    for (int t = 0; t < 4; t++) {
        int i = tid + t * 128;
        int row = i >> 3;
        int c16 = i & 7;
        uint32_t doff = swz8(row, c16);
        size_t goff = gbase + (size_t)row * KVDIM + c16 * 8;
        CP_ASYNC16(sbase + 0     + doff, Kh + goff);
        CP_ASYNC16(sbase + 8192  + doff, Kl + goff);
        CP_ASYNC16(sbase + 16384 + doff, Vh + goff);
        CP_ASYNC16(sbase + 24576 + doff, Vl + goff);
    }
}

__global__ void __launch_bounds__(128) flash_mma(
    const __nv_bfloat16* __restrict__ Qh, const __nv_bfloat16* __restrict__ Ql,
    const __nv_bfloat16* __restrict__ Kh, const __nv_bfloat16* __restrict__ Kl,
    const __nv_bfloat16* __restrict__ Vh, const __nv_bfloat16* __restrict__ Vl,
    __nv_bfloat16* __restrict__ Oh, __nv_bfloat16* __restrict__ Ol)
{
    extern __shared__ char smem[];
    uint32_t sb = smem_u32(smem);
    const int qt = blockIdx.x;
    const int h  = blockIdx.y;
    const int b  = blockIdx.z;
    const int kvh = h / GROUPS;
    const int tid = threadIdx.x;
    const int lane = tid & 31;
    const int w = tid >> 5;
    const int qbase = qt * 128;

#pragma unroll
    for (int t = 0; t < 8; t++) {
        int i = tid + t * 128;
        int row = i >> 3;
        int c16 = i & 7;
        uint32_t doff = swz8(row, c16);
        size_t goff = (size_t)(b * SEQ + qbase + row) * DMODEL + h * HDIM + c16 * 8;
        CP_ASYNC16(sb + doff, Qh + goff);
        CP_ASYNC16(sb + 16384 + doff, Ql + goff);
    }
    size_t kvg0 = (size_t)(b * SEQ) * KVDIM + kvh * HDIM;
    stage_kv(Kh, Kl, Vh, Vl, sb + FQ_SMEM, kvg0, tid);
    CP_COMMIT();

    float acc[2][8][4];
#pragma unroll
    for (int mt = 0; mt < 2; mt++)
#pragma unroll
        for (int nt = 0; nt < 8; nt++)
#pragma unroll
            for (int e = 0; e < 4; e++) acc[mt][nt][e] = 0.f;
    float mrow[2][2] = {{-CUDART_INF_F, -CUDART_INF_F},
                        {-CUDART_INF_F, -CUDART_INF_F}};
    float lrow[2][2] = {{0.f, 0.f}, {0.f, 0.f}};

    const int nb = 2 * qt + 2;
    for (int c = 0; c < nb; c++) {
        if (c + 1 < nb) {
            stage_kv(Kh, Kl, Vh, Vl, sb + FQ_SMEM + ((c + 1) & 1) * KV_BUF,
                     kvg0 + (size_t)(c + 1) * 64 * KVDIM, tid);
            CP_COMMIT();
            CP_WAIT1();
        } else {
            CP_WAIT0();
        }
        __syncthreads();

        uint32_t sk = sb + FQ_SMEM + (c & 1) * KV_BUF;

        float S[2][8][4];
#pragma unroll
        for (int mt = 0; mt < 2; mt++)
#pragma unroll
            for (int nt = 0; nt < 8; nt++)
#pragma unroll
                for (int e = 0; e < 4; e++) S[mt][nt][e] = 0.f;

#pragma unroll
        for (int ks = 0; ks < 4; ks++) {
            uint32_t qh[2][4], ql[2][4];
#pragma unroll
            for (int mt = 0; mt < 2; mt++) {
                int row = w * 32 + mt * 16 + (lane & 15);
                int c16 = ks * 2 + (lane >> 4);
                uint32_t off = swz8(row, c16);
                LDMATRIX_X4(qh[mt][0], qh[mt][1], qh[mt][2], qh[mt][3], sb + off);
                LDMATRIX_X4(ql[mt][0], ql[mt][1], ql[mt][2], ql[mt][3],
                            sb + 16384 + off);
            }
#pragma unroll
            for (int np = 0; np < 4; np++) {
                int row = np * 16 + ((lane >> 4) * 8) + (lane & 7);
                int c16 = ks * 2 + ((lane >> 3) & 1);
                uint32_t off = swz8(row, c16);
                uint32_t kh[4], kl[4];
                LDMATRIX_X4(kh[0], kh[1], kh[2], kh[3], sk + off);
                LDMATRIX_X4(kl[0], kl[1], kl[2], kl[3], sk + 8192 + off);
#pragma unroll
                for (int mt = 0; mt < 2; mt++) {
                    MMA16816(S[mt][2 * np],     qh[mt], (kh + 0));
                    MMA16816(S[mt][2 * np + 1], qh[mt], (kh + 2));
                    MMA16816(S[mt][2 * np],     qh[mt], (kl + 0));
                    MMA16816(S[mt][2 * np + 1], qh[mt], (kl + 2));
                    MMA16816(S[mt][2 * np],     ql[mt], (kh + 0));
                    MMA16816(S[mt][2 * np + 1], ql[mt], (kh + 2));
                }
            }
        }

        if (c >= 2 * qt) {
            int kb = c * 64;
#pragma unroll
            for (int mt = 0; mt < 2; mt++) {
                int r0 = qbase + w * 32 + mt * 16 + (lane >> 2);
#pragma unroll
                for (int nt = 0; nt < 8; nt++) {
                    int key = kb + nt * 8 + (lane & 3) * 2;
                    if (key > r0)     S[mt][nt][0] = -CUDART_INF_F;
                    if (key + 1 > r0) S[mt][nt][1] = -CUDART_INF_F;
                    if (key > r0 + 8)     S[mt][nt][2] = -CUDART_INF_F;
                    if (key + 1 > r0 + 8) S[mt][nt][3] = -CUDART_INF_F;
                }
            }
        }

        uint32_t aPh[2][4][4], aPl[2][4][4];
#pragma unroll
        for (int mt = 0; mt < 2; mt++) {
#pragma unroll
            for (int e2 = 0; e2 < 2; e2++) {
                float mx = -CUDART_INF_F;
#pragma unroll
                for (int nt = 0; nt < 8; nt++)
                    mx = fmaxf(mx, fmaxf(S[mt][nt][2 * e2], S[mt][nt][2 * e2 + 1]));
                mx = fmaxf(mx, __shfl_xor_sync(0xffffffffu, mx, 1));
                mx = fmaxf(mx, __shfl_xor_sync(0xffffffffu, mx, 2));
                float mn = fmaxf(mrow[mt][e2], mx);
                float alpha = __expf(mrow[mt][e2] - mn);
                mrow[mt][e2] = mn;
                float sum = 0.f;
#pragma unroll
                for (int nt = 0; nt < 8; nt++) {
                    float p0 = __expf(S[mt][nt][2 * e2] - mn);
                    float p1 = __expf(S[mt][nt][2 * e2 + 1] - mn);
                    S[mt][nt][2 * e2] = p0;
                    S[mt][nt][2 * e2 + 1] = p1;
                    sum += p0 + p1;
                }
                sum += __shfl_xor_sync(0xffffffffu, sum, 1);
                sum += __shfl_xor_sync(0xffffffffu, sum, 2);
                lrow[mt][e2] = lrow[mt][e2] * alpha + sum;
#pragma unroll
                for (int nt = 0; nt < 8; nt++) {
                    acc[mt][nt][2 * e2] *= alpha;
                    acc[mt][nt][2 * e2 + 1] *= alpha;
                }
            }
#pragma unroll
            for (int kc = 0; kc < 4; kc++) {
#pragma unroll
                for (int r = 0; r < 4; r++) {
                    int nt = 2 * kc + (r >> 1);
                    int e0 = (r & 1) * 2;
                    float p0 = S[mt][nt][e0], p1 = S[mt][nt][e0 + 1];
                    __nv_bfloat162 hh = __floats2bfloat162_rn(p0, p1);
                    float r0 = p0 - __bfloat162float(hh.x);
                    float r1 = p1 - __bfloat162float(hh.y);
                    __nv_bfloat162 ll = __floats2bfloat162_rn(r0, r1);
                    aPh[mt][kc][r] = *reinterpret_cast<uint32_t*>(&hh);
                    aPl[mt][kc][r] = *reinterpret_cast<uint32_t*>(&ll);
                }
            }
        }

#pragma unroll
        for (int kc = 0; kc < 4; kc++) {
#pragma unroll
            for (int dp = 0; dp < 4; dp++) {
                int row = kc * 16 + ((lane >> 3) & 1) * 8 + (lane & 7);
                int c16 = dp * 2 + (lane >> 4);
                uint32_t off = swz8(row, c16);
                uint32_t vh[4], vl[4];
                LDMATRIX_X4T(vh[0], vh[1], vh[2], vh[3], sk + 16384 + off);
                LDMATRIX_X4T(vl[0], vl[1], vl[2], vl[3], sk + 24576 + off);
#pragma unroll
                for (int mt = 0; mt < 2; mt++) {
                    MMA16816(acc[mt][2 * dp],     aPh[mt][kc], (vh + 0));
                    MMA16816(acc[mt][2 * dp + 1], aPh[mt][kc], (vh + 2));
                    MMA16816(acc[mt][2 * dp],     aPh[mt][kc], (vl + 0));
                    MMA16816(acc[mt][2 * dp + 1], aPh[mt][kc], (vl + 2));
                    MMA16816(acc[mt][2 * dp],     aPl[mt][kc], (vh + 0));
                    MMA16816(acc[mt][2 * dp + 1], aPl[mt][kc], (vh + 2));
                }
            }
        }
        __syncthreads();
    }

#pragma unroll
    for (int mt = 0; mt < 2; mt++) {
        float inv0 = 1.0f / lrow[mt][0];
        float inv1 = 1.0f / lrow[mt][1];
        int r0 = qbase + w * 32 + mt * 16 + (lane >> 2);
        size_t t0 = (size_t)(b * SEQ + r0) * DMODEL + h * HDIM;
        size_t t1 = t0 + 8 * DMODEL;
#pragma unroll
        for (int nt = 0; nt < 8; nt++) {
            int d = nt * 8 + (lane & 3) * 2;
            float v0 = acc[mt][nt][0] * inv0, v1 = acc[mt][nt][1] * inv0;
            float v2 = acc[mt][nt][2] * inv1, v3 = acc[mt][nt][3] * inv1;
            __nv_bfloat162 h01 = __floats2bfloat162_rn(v0, v1);
            __nv_bfloat162 h23 = __floats2bfloat162_rn(v2, v3);
            __nv_bfloat162 l01 = __floats2bfloat162_rn(
                v0 - __bfloat162float(h01.x), v1 - __bfloat162float(h01.y));
            __nv_bfloat162 l23 = __floats2bfloat162_rn(
                v2 - __bfloat162float(h23.x), v3 - __bfloat162float(h23.y));
            *reinterpret_cast<__nv_bfloat162*>(Oh + t0 + d) = h01;
            *reinterpret_cast<__nv_bfloat162*>(Oh + t1 + d) = h23;
            *reinterpret_cast<__nv_bfloat162*>(Ol + t0 + d) = l01;
            *reinterpret_cast<__nv_bfloat162*>(Ol + t1 + d) = l23;
        }
    }
}

// ---------------- launch ----------------------------------------------------
extern "C" void kernel_launch(void* const* d_in, const int* in_sizes, int n_in,
                              void* d_out, int out_size)
{
    const float* hidden = (const float*)d_in[0];
    const float* cs     = (const float*)d_in[1];
    const float* sn     = (const float*)d_in[2];
    const float* Wq     = (const float*)d_in[3];
    const float* Wk     = (const float*)d_in[4];
    const float* Wv     = (const float*)d_in[5];
    const float* Wo     = (const float*)d_in[6];
    float* out          = (float*)d_out;

    __nv_bfloat16* Ah = nullptr; cudaGetSymbolAddress((void**)&Ah, g_Ahi);
    __nv_bfloat16* Al = nullptr; cudaGetSymbolAddress((void**)&Al, g_Alo);
    __nv_bfloat16* Bh = nullptr; cudaGetSymbolAddress((void**)&Bh, g_Bhi);
    __nv_bfloat16* Bl = nullptr; cudaGetSymbolAddress((void**)&Bl, g_Blo);
    __nv_bfloat16* Qh = nullptr; cudaGetSymbolAddress((void**)&Qh, g_Qh);
    __nv_bfloat16* Ql = nullptr; cudaGetSymbolAddress((void**)&Ql, g_Ql);
    __nv_bfloat16* Kh = nullptr; cudaGetSymbolAddress((void**)&Kh, g_Kh);
    __nv_bfloat16* Kl = nullptr; cudaGetSymbolAddress((void**)&Kl, g_Kl);
    __nv_bfloat16* Vh = nullptr; cudaGetSymbolAddress((void**)&Vh, g_Vh);
    __nv_bfloat16* Vl = nullptr; cudaGetSymbolAddress((void**)&Vl, g_Vl);

    static bool attr_set = false;
    if (!attr_set) {
        cudaFuncSetAttribute(gemm_mma<0>, cudaFuncAttributeMaxDynamicSharedMemorySize,
                             GEMM_SMEM);
        cudaFuncSetAttribute(gemm_mma<1>, cudaFuncAttributeMaxDynamicSharedMemorySize,
                             GEMM_SMEM);
        cudaFuncSetAttribute(flash_mma, cudaFuncAttributeMaxDynamicSharedMemorySize,
                             FLASH_SMEM);
        attr_set = true;
    }

    const int n4 = TOK * DMODEL / 4;

    // hidden -> bf16 hi/lo (A operand)
    split_kernel<<<n4 / 256, 256>>>(hidden, (__nv_bfloat162*)Ah,
                                    (__nv_bfloat162*)Al, n4);

    // B = [WqT ; WkT ; WvT]
    transpose_split<<<dim3(DMODEL / 32, DMODEL / 32), dim3(32, 8)>>>(Wq, Bh, Bl, DMODEL, 0);
    transpose_split<<<dim3(KVDIM / 32, DMODEL / 32), dim3(32, 8)>>>(Wk, Bh, Bl, KVDIM, DMODEL);
    transpose_split<<<dim3(KVDIM / 32, DMODEL / 32), dim3(32, 8)>>>(Wv, Bh, Bl, KVDIM, DMODEL + KVDIM);

    // fused QKV GEMM: rope + scale + bf16 hi/lo split in the epilogue
    gemm_mma<1><<<dim3(QKVN / BN, TOK / BM), 256, GEMM_SMEM>>>(
        Ah, Al, Bh, Bl, nullptr, QKVN, cs, sn, Qh, Ql, Kh, Kl, Vh, Vl);

    // Wo transpose (Bh/Bl free after QKV GEMM)
    transpose_split<<<dim3(DMODEL / 32, DMODEL / 32), dim3(32, 8)>>>(Wo, Bh, Bl, DMODEL, 0);

    // flash attention -> writes bf16 hi/lo straight into the Wo-GEMM A buffers
    {
        dim3 grid(SEQ / 128, NHEADS, BSZ);
        flash_mma<<<grid, 128, FLASH_SMEM>>>(Qh, Ql, Kh, Kl, Vh, Vl, Ah, Al);
    }

    // out = attn @ Wo
    gemm_mma<0><<<dim3(DMODEL / BN, TOK / BM), 256, GEMM_SMEM>>>(
        Ah, Al, Bh, Bl, out, DMODEL, nullptr, nullptr,
        nullptr, nullptr, nullptr, nullptr, nullptr, nullptr);
}

// round 12
// speedup vs baseline: 1.5084x; 1.5084x over previous
#include <cuda_runtime.h>
#include <cuda_bf16.h>
#include <cstdint>
#include <math_constants.h>

// Problem constants
#define BSZ 4
#define SEQ 1024
#define TOK (BSZ * SEQ)          // 4096
#define DMODEL 2048
#define NHEADS 32
#define NKV 8
#define HDIM 64
#define GROUPS (NHEADS / NKV)     // 4
#define KVDIM (NKV * HDIM)        // 512
#define QKVN (DMODEL + 2 * KVDIM) // 3072
#define ATTN_SCALE 0.125f

// ---------------- scratch (static device globals; no allocation) ----------
__device__ float g_QKV[(size_t)TOK * QKVN];
__device__ __align__(16) __nv_bfloat16 g_Ahi[(size_t)TOK * DMODEL];
__device__ __align__(16) __nv_bfloat16 g_Alo[(size_t)TOK * DMODEL];
__device__ __align__(16) __nv_bfloat16 g_Bhi[(size_t)QKVN * DMODEL]; // [N,K]
__device__ __align__(16) __nv_bfloat16 g_Blo[(size_t)QKVN * DMODEL];
__device__ __align__(16) __nv_bfloat16 g_Qh[(size_t)TOK * DMODEL];
__device__ __align__(16) __nv_bfloat16 g_Ql[(size_t)TOK * DMODEL];
__device__ __align__(16) __nv_bfloat16 g_Kh[(size_t)TOK * KVDIM];
__device__ __align__(16) __nv_bfloat16 g_Kl[(size_t)TOK * KVDIM];
__device__ __align__(16) __nv_bfloat16 g_Vh[(size_t)TOK * KVDIM];
__device__ __align__(16) __nv_bfloat16 g_Vl[(size_t)TOK * KVDIM];

// =================== PTX helpers (compute_103-safe) =========================
__device__ __forceinline__ uint32_t smem_u32(const void* p) {
    uint32_t a;
    asm("{ .reg .u64 t; cvta.to.shared.u64 t, %1; cvt.u32.u64 %0, t; }"
        : "=r"(a) : "l"(p));
    return a;
}

#define CP_ASYNC16(dst, src) \
    asm volatile("cp.async.cg.shared.global [%0], [%1], 16;" \
                 :: "r"(dst), "l"(src) : "memory")
#define CP_COMMIT() asm volatile("cp.async.commit_group;" ::: "memory")
#define CP_WAIT2()  asm volatile("cp.async.wait_group 2;" ::: "memory")
#define CP_WAIT1()  asm volatile("cp.async.wait_group 1;" ::: "memory")
#define CP_WAIT0()  asm volatile("cp.async.wait_group 0;" ::: "memory")

#define LDMATRIX_X4(r0, r1, r2, r3, addr) \
    asm volatile("ldmatrix.sync.aligned.m8n8.x4.shared.b16 {%0,%1,%2,%3}, [%4];" \
                 : "=r"(r0), "=r"(r1), "=r"(r2), "=r"(r3) : "r"(addr))

#define LDMATRIX_X4T(r0, r1, r2, r3, addr) \
    asm volatile("ldmatrix.sync.aligned.m8n8.x4.trans.shared.b16 {%0,%1,%2,%3}, [%4];" \
                 : "=r"(r0), "=r"(r1), "=r"(r2), "=r"(r3) : "r"(addr))

#define MMA16816(d, a, b) \
    asm volatile("mma.sync.aligned.m16n8k16.row.col.f32.bf16.bf16.f32 " \
                 "{%0,%1,%2,%3}, {%4,%5,%6,%7}, {%8,%9}, {%0,%1,%2,%3};" \
                 : "+f"((d)[0]), "+f"((d)[1]), "+f"((d)[2]), "+f"((d)[3]) \
                 : "r"((a)[0]), "r"((a)[1]), "r"((a)[2]), "r"((a)[3]), \
                   "r"((b)[0]), "r"((b)[1]))

// 128-byte rows, 8-chunk swizzle
__device__ __forceinline__ uint32_t swz8(int row, int c16) {
    return (uint32_t)(row * 128 + ((c16 ^ (row & 7)) * 16));
}

// =================== conversion kernels (verified R8) =======================
__global__ void split_kernel(const float* __restrict__ A,
                             __nv_bfloat162* __restrict__ H,
                             __nv_bfloat162* __restrict__ L, int n4)
{
    int i = blockIdx.x * blockDim.x + threadIdx.x;
    if (i >= n4) return;
    float4 v = reinterpret_cast<const float4*>(A)[i];
    __nv_bfloat16 h0 = __float2bfloat16(v.x);
    __nv_bfloat16 h1 = __float2bfloat16(v.y);
    __nv_bfloat16 h2 = __float2bfloat16(v.z);
    __nv_bfloat16 h3 = __float2bfloat16(v.w);
    __nv_bfloat16 l0 = __float2bfloat16(v.x - __bfloat162float(h0));
    __nv_bfloat16 l1 = __float2bfloat16(v.y - __bfloat162float(h1));
    __nv_bfloat16 l2 = __float2bfloat16(v.z - __bfloat162float(h2));
    __nv_bfloat16 l3 = __float2bfloat16(v.w - __bfloat162float(h3));
    H[2 * i]     = __nv_bfloat162(h0, h1);
    H[2 * i + 1] = __nv_bfloat162(h2, h3);
    L[2 * i]     = __nv_bfloat162(l0, l1);
    L[2 * i + 1] = __nv_bfloat162(l2, l3);
}

__global__ void split_strided(const float* __restrict__ X, int xstride, int xoff,
                              __nv_bfloat162* __restrict__ H,
                              __nv_bfloat162* __restrict__ L, int cols)
{
    int idx = blockIdx.x * blockDim.x + threadIdx.x;
    int c4 = cols / 4;
    int row = idx / c4;
    int c = idx % c4;
    if (row >= TOK) return;
    float4 v = *reinterpret_cast<const float4*>(X + (size_t)row * xstride + xoff + c * 4);
    __nv_bfloat16 h0 = __float2bfloat16(v.x);
    __nv_bfloat16 h1 = __float2bfloat16(v.y);
    __nv_bfloat16 h2 = __float2bfloat16(v.z);
    __nv_bfloat16 h3 = __float2bfloat16(v.w);
    size_t o = ((size_t)row * cols + c * 4) / 2;
    H[o]     = __nv_bfloat162(h0, h1);
    H[o + 1] = __nv_bfloat162(h2, h3);
    L[o]     = __nv_bfloat162(__float2bfloat16(v.x - __bfloat162float(h0)),
                              __float2bfloat16(v.y - __bfloat162float(h1)));
    L[o + 1] = __nv_bfloat162(__float2bfloat16(v.z - __bfloat162float(h2)),
                              __float2bfloat16(v.w - __bfloat162float(h3)));
}

__global__ void transpose_split(const float* __restrict__ W,
                                __nv_bfloat16* __restrict__ Th,
                                __nv_bfloat16* __restrict__ Tl, int N, int rowoff)
{
    __shared__ float tile[32][33];
    int n = blockIdx.x * 32 + threadIdx.x;
    int k = blockIdx.y * 32 + threadIdx.y;
#pragma unroll
    for (int j = 0; j < 32; j += 8)
        tile[threadIdx.y + j][threadIdx.x] = W[(size_t)(k + j) * N + n];
    __syncthreads();
    int k2 = blockIdx.y * 32 + threadIdx.x;
    int n2 = blockIdx.x * 32 + threadIdx.y + rowoff;
#pragma unroll
    for (int j = 0; j < 32; j += 8) {
        float v = tile[threadIdx.x][threadIdx.y + j];
        __nv_bfloat16 h = __float2bfloat16(v);
        Th[(size_t)(n2 + j) * DMODEL + k2] = h;
        Tl[(size_t)(n2 + j) * DMODEL + k2] =
            __float2bfloat16(v - __bfloat162float(h));
    }
}

__global__ void rope_split(const float* __restrict__ X, int xstride, int xoff,
                           const float* __restrict__ cs,
                           const float* __restrict__ sn,
                           __nv_bfloat16* __restrict__ Xh,
                           __nv_bfloat16* __restrict__ Xl,
                           int H, float scale)
{
    int idx = blockIdx.x * blockDim.x + threadIdx.x;
    int total = TOK * H * 32;
    if (idx >= total) return;
    int i = idx & 31;
    int h = (idx >> 5) % H;
    int t = idx / (32 * H);
    float c = cs[t * 32 + i];
    float s = sn[t * 32 + i];
    const float* in = X + (size_t)t * xstride + xoff + h * HDIM;
    size_t ob = (size_t)t * (H * HDIM) + h * HDIM;
    float x1 = in[i], x2 = in[i + 32];
    float y1 = (x1 * c - x2 * s) * scale;
    float y2 = (x2 * c + x1 * s) * scale;
    __nv_bfloat16 h1 = __float2bfloat16(y1);
    __nv_bfloat16 h2 = __float2bfloat16(y2);
    Xh[ob + i]      = h1;
    Xh[ob + i + 32] = h2;
    Xl[ob + i]      = __float2bfloat16(y1 - __bfloat162float(h1));
    Xl[ob + i + 32] = __float2bfloat16(y2 - __bfloat162float(h2));
}

// =================== HMMA GEMM: R8 schedule + fragment double-buffering =====
#define BM 128
#define BN 128
#define BK 64
#define TILE_B (128 * BK * 2)          // 16384
#define STAGE_B (4 * TILE_B)           // 65536
#define GEMM_SMEM (3 * STAGE_B)        // 196608

__device__ __forceinline__ void stage_load(
    const __nv_bfloat16* __restrict__ aH, const __nv_bfloat16* __restrict__ aL,
    const __nv_bfloat16* __restrict__ bH, const __nv_bfloat16* __restrict__ bL,
    uint32_t sbase, int k0, int tid)
{
#pragma unroll
    for (int j = 0; j < 4; j++) {
        int i = tid + j * 256;
        int row = i >> 3;
        int c16 = i & 7;
        uint32_t doff = swz8(row, c16);
        size_t goff = (size_t)row * DMODEL + k0 + c16 * 8;
        CP_ASYNC16(sbase + 0 * TILE_B + doff, aH + goff);
        CP_ASYNC16(sbase + 1 * TILE_B + doff, aL + goff);
        CP_ASYNC16(sbase + 2 * TILE_B + doff, bH + goff);
        CP_ASYNC16(sbase + 3 * TILE_B + doff, bL + goff);
    }
}

// load all fragments for k-slice `ks` into buffer slot `b`
#define LOAD_FRAGS(ks, b) do {                                                 \
    _Pragma("unroll")                                                          \
    for (int mt = 0; mt < 4; mt++) {                                           \
        int row = wm * 64 + mt * 16 + (lane & 15);                             \
        int c16 = (ks) * 2 + (lane >> 4);                                      \
        uint32_t off = swz8(row, c16);                                         \
        LDMATRIX_X4(fAh[b][mt][0], fAh[b][mt][1], fAh[b][mt][2], fAh[b][mt][3],\
                    st + 0 * TILE_B + off);                                    \
        LDMATRIX_X4(fAl[b][mt][0], fAl[b][mt][1], fAl[b][mt][2], fAl[b][mt][3],\
                    st + 1 * TILE_B + off);                                    \
    }                                                                          \
    _Pragma("unroll")                                                          \
    for (int pr = 0; pr < 2; pr++) {                                           \
        int nrel = wn * 32 + pr * 16 + ((lane >> 4) * 8 + (lane & 7));         \
        int c16 = (ks) * 2 + ((lane >> 3) & 1);                                \
        uint32_t off = swz8(nrel, c16);                                        \
        LDMATRIX_X4(fBh[b][2 * pr][0], fBh[b][2 * pr][1],                      \
                    fBh[b][2 * pr + 1][0], fBh[b][2 * pr + 1][1],              \
                    st + 2 * TILE_B + off);                                    \
        LDMATRIX_X4(fBl[b][2 * pr][0], fBl[b][2 * pr][1],                      \
                    fBl[b][2 * pr + 1][0], fBl[b][2 * pr + 1][1],              \
                    st + 3 * TILE_B + off);                                    \
    }                                                                          \
} while (0)

__global__ void __launch_bounds__(256, 1) gemm_mma(
    const __nv_bfloat16* __restrict__ Ahi, const __nv_bfloat16* __restrict__ Alo,
    const __nv_bfloat16* __restrict__ Bhi, const __nv_bfloat16* __restrict__ Blo,
    float* __restrict__ C, int N)
{
    extern __shared__ char smem[];
    uint32_t sb = smem_u32(smem);
    const int tid = threadIdx.x;
    const int lane = tid & 31;
    const int wid = tid >> 5;
    const int wm = wid >> 2;
    const int wn = wid & 3;
    const int brow = blockIdx.y * BM;
    const int bcol = blockIdx.x * BN;

    const __nv_bfloat16* aH = Ahi + (size_t)brow * DMODEL;
    const __nv_bfloat16* aL = Alo + (size_t)brow * DMODEL;
    const __nv_bfloat16* bH = Bhi + (size_t)bcol * DMODEL;
    const __nv_bfloat16* bL = Blo + (size_t)bcol * DMODEL;

    float acc[4][4][4];
#pragma unroll
    for (int i = 0; i < 4; i++)
#pragma unroll
        for (int j = 0; j < 4; j++)
#pragma unroll
            for (int q = 0; q < 4; q++) acc[i][j][q] = 0.f;

    const int NC = DMODEL / BK;   // 32
#pragma unroll
    for (int s = 0; s < 3; s++) {
        stage_load(aH, aL, bH, bL, sb + s * STAGE_B, s * BK, tid);
        CP_COMMIT();
    }

    uint32_t fAh[2][4][4], fAl[2][4][4];
    uint32_t fBh[2][4][2], fBl[2][4][2];

    for (int c = 0; c < NC; c++) {
        if (c + 2 < NC)      CP_WAIT2();
        else if (c + 1 < NC) CP_WAIT1();
        else                 CP_WAIT0();
        __syncthreads();

        uint32_t st = sb + (uint32_t)(c % 3) * STAGE_B;

        LOAD_FRAGS(0, 0);
#pragma unroll
        for (int ks = 0; ks < 4; ks++) {
            const int cur = ks & 1;
            if (ks < 3) LOAD_FRAGS(ks + 1, (ks + 1) & 1);
#pragma unroll
            for (int mt = 0; mt < 4; mt++)
#pragma unroll
                for (int nt = 0; nt < 4; nt++) {
                    MMA16816(acc[mt][nt], fAh[cur][mt], fBh[cur][nt]);
                    MMA16816(acc[mt][nt], fAh[cur][mt], fBl[cur][nt]);
                    MMA16816(acc[mt][nt], fAl[cur][mt], fBh[cur][nt]);
                }
        }
        __syncthreads();
        if (c + 3 < NC) {
            stage_load(aH, aL, bH, bL, st, (c + 3) * BK, tid);
            CP_COMMIT();
        }
    }

#pragma unroll
    for (int mt = 0; mt < 4; mt++) {
#pragma unroll
        for (int nt = 0; nt < 4; nt++) {
            int m = brow + wm * 64 + mt * 16 + (lane >> 2);
            int n = bcol + wn * 32 + nt * 8 + (lane & 3) * 2;
            float2 v0 = make_float2(acc[mt][nt][0], acc[mt][nt][1]);
            float2 v1 = make_float2(acc[mt][nt][2], acc[mt][nt][3]);
            *reinterpret_cast<float2*>(C + (size_t)m * N + n) = v0;
            *reinterpret_cast<float2*>(C + (size_t)(m + 8) * N + n) = v1;
        }
    }
}

// =================== tensor-core flash attention (verified R8) ==============
#define FQ_SMEM 32768
#define KV_BUF  32768
#define FLASH_SMEM (FQ_SMEM + 2 * KV_BUF)

__device__ __forceinline__ void stage_kv(
    const __nv_bfloat16* __restrict__ Kh, const __nv_bfloat16* __restrict__ Kl,
    const __nv_bfloat16* __restrict__ Vh, const __nv_bfloat16* __restrict__ Vl,
    uint32_t sbase, size_t gbase, int tid)
{
#pragma unroll
    for (int t = 0; t < 4; t++) {
        int i = tid + t * 128;
        int row = i >> 3;
        int c16 = i & 7;
        uint32_t doff = swz8(row, c16);
        size_t goff = gbase + (size_t)row * KVDIM + c16 * 8;
        CP_ASYNC16(sbase + 0     + doff, Kh + goff);
        CP_ASYNC16(sbase + 8192  + doff, Kl + goff);
        CP_ASYNC16(sbase + 16384 + doff, Vh + goff);
        CP_ASYNC16(sbase + 24576 + doff, Vl + goff);
    }
}

__global__ void __launch_bounds__(128) flash_mma(
    const __nv_bfloat16* __restrict__ Qh, const __nv_bfloat16* __restrict__ Ql,
    const __nv_bfloat16* __restrict__ Kh, const __nv_bfloat16* __restrict__ Kl,
    const __nv_bfloat16* __restrict__ Vh, const __nv_bfloat16* __restrict__ Vl,
    __nv_bfloat16* __restrict__ Oh, __nv_bfloat16* __restrict__ Ol)
{
    extern __shared__ char smem[];
    uint32_t sb = smem_u32(smem);
    const int qt = blockIdx.x;
    const int h  = blockIdx.y;
    const int b  = blockIdx.z;
    const int kvh = h / GROUPS;
    const int tid = threadIdx.x;
    const int lane = tid & 31;
    const int w = tid >> 5;
    const int qbase = qt * 128;

#pragma unroll
    for (int t = 0; t < 8; t++) {
        int i = tid + t * 128;
        int row = i >> 3;
        int c16 = i & 7;
        uint32_t doff = swz8(row, c16);
        size_t goff = (size_t)(b * SEQ + qbase + row) * DMODEL + h * HDIM + c16 * 8;
        CP_ASYNC16(sb + doff, Qh + goff);
        CP_ASYNC16(sb + 16384 + doff, Ql + goff);
    }
    size_t kvg0 = (size_t)(b * SEQ) * KVDIM + kvh * HDIM;
    stage_kv(Kh, Kl, Vh, Vl, sb + FQ_SMEM, kvg0, tid);
    CP_COMMIT();

    float acc[2][8][4];
#pragma unroll
    for (int mt = 0; mt < 2; mt++)
#pragma unroll
        for (int nt = 0; nt < 8; nt++)
#pragma unroll
            for (int e = 0; e < 4; e++) acc[mt][nt][e] = 0.f;
    float mrow[2][2] = {{-CUDART_INF_F, -CUDART_INF_F},
                        {-CUDART_INF_F, -CUDART_INF_F}};
    float lrow[2][2] = {{0.f, 0.f}, {0.f, 0.f}};

    const int nb = 2 * qt + 2;
    for (int c = 0; c < nb; c++) {
        if (c + 1 < nb) {
            stage_kv(Kh, Kl, Vh, Vl, sb + FQ_SMEM + ((c + 1) & 1) * KV_BUF,
                     kvg0 + (size_t)(c + 1) * 64 * KVDIM, tid);
            CP_COMMIT();
            CP_WAIT1();
        } else {
            CP_WAIT0();
        }
        __syncthreads();

        uint32_t sk = sb + FQ_SMEM + (c & 1) * KV_BUF;

        float S[2][8][4];
#pragma unroll
        for (int mt = 0; mt < 2; mt++)
#pragma unroll
            for (int nt = 0; nt < 8; nt++)
#pragma unroll
                for (int e = 0; e < 4; e++) S[mt][nt][e] = 0.f;

#pragma unroll
        for (int ks = 0; ks < 4; ks++) {
            uint32_t qh[2][4], ql[2][4];
#pragma unroll
            for (int mt = 0; mt < 2; mt++) {
                int row = w * 32 + mt * 16 + (lane & 15);
                int c16 = ks * 2 + (lane >> 4);
                uint32_t off = swz8(row, c16);
                LDMATRIX_X4(qh[mt][0], qh[mt][1], qh[mt][2], qh[mt][3], sb + off);
                LDMATRIX_X4(ql[mt][0], ql[mt][1], ql[mt][2], ql[mt][3],
                            sb + 16384 + off);
            }
#pragma unroll
            for (int np = 0; np < 4; np++) {
                int row = np * 16 + ((lane >> 4) * 8) + (lane & 7);
                int c16 = ks * 2 + ((lane >> 3) & 1);
                uint32_t off = swz8(row, c16);
                uint32_t kh[4], kl[4];
                LDMATRIX_X4(kh[0], kh[1], kh[2], kh[3], sk + off);
                LDMATRIX_X4(kl[0], kl[1], kl[2], kl[3], sk + 8192 + off);
#pragma unroll
                for (int mt = 0; mt < 2; mt++) {
                    MMA16816(S[mt][2 * np],     qh[mt], (kh + 0));
                    MMA16816(S[mt][2 * np + 1], qh[mt], (kh + 2));
                    MMA16816(S[mt][2 * np],     qh[mt], (kl + 0));
                    MMA16816(S[mt][2 * np + 1], qh[mt], (kl + 2));
                    MMA16816(S[mt][2 * np],     ql[mt], (kh + 0));
                    MMA16816(S[mt][2 * np + 1], ql[mt], (kh + 2));
                }
            }
        }

        if (c >= 2 * qt) {
            int kb = c * 64;
#pragma unroll
            for (int mt = 0; mt < 2; mt++) {
                int r0 = qbase + w * 32 + mt * 16 + (lane >> 2);
#pragma unroll
                for (int nt = 0; nt < 8; nt++) {
                    int key = kb + nt * 8 + (lane & 3) * 2;
                    if (key > r0)     S[mt][nt][0] = -CUDART_INF_F;
                    if (key + 1 > r0) S[mt][nt][1] = -CUDART_INF_F;
                    if (key > r0 + 8)     S[mt][nt][2] = -CUDART_INF_F;
                    if (key + 1 > r0 + 8) S[mt][nt][3] = -CUDART_INF_F;
                }
            }
        }

        uint32_t aPh[2][4][4], aPl[2][4][4];
#pragma unroll
        for (int mt = 0; mt < 2; mt++) {
#pragma unroll
            for (int e2 = 0; e2 < 2; e2++) {
                float mx = -CUDART_INF_F;
#pragma unroll
                for (int nt = 0; nt < 8; nt++)
                    mx = fmaxf(mx, fmaxf(S[mt][nt][2 * e2], S[mt][nt][2 * e2 + 1]));
                mx = fmaxf(mx, __shfl_xor_sync(0xffffffffu, mx, 1));
                mx = fmaxf(mx, __shfl_xor_sync(0xffffffffu, mx, 2));
                float mn = fmaxf(mrow[mt][e2], mx);
                float alpha = __expf(mrow[mt][e2] - mn);
                mrow[mt][e2] = mn;
                float sum = 0.f;
#pragma unroll
                for (int nt = 0; nt < 8; nt++) {
                    float p0 = __expf(S[mt][nt][2 * e2] - mn);
                    float p1 = __expf(S[mt][nt][2 * e2 + 1] - mn);
                    S[mt][nt][2 * e2] = p0;
                    S[mt][nt][2 * e2 + 1] = p1;
                    sum += p0 + p1;
                }
                sum += __shfl_xor_sync(0xffffffffu, sum, 1);
                sum += __shfl_xor_sync(0xffffffffu, sum, 2);
                lrow[mt][e2] = lrow[mt][e2] * alpha + sum;
#pragma unroll
                for (int nt = 0; nt < 8; nt++) {
                    acc[mt][nt][2 * e2] *= alpha;
                    acc[mt][nt][2 * e2 + 1] *= alpha;
                }
            }
#pragma unroll
            for (int kc = 0; kc < 4; kc++) {
#pragma unroll
                for (int r = 0; r < 4; r++) {
                    int nt = 2 * kc + (r >> 1);
                    int e0 = (r & 1) * 2;
                    float p0 = S[mt][nt][e0], p1 = S[mt][nt][e0 + 1];
                    __nv_bfloat162 hh = __floats2bfloat162_rn(p0, p1);
                    float r0 = p0 - __bfloat162float(hh.x);
                    float r1 = p1 - __bfloat162float(hh.y);
                    __nv_bfloat162 ll = __floats2bfloat162_rn(r0, r1);
                    aPh[mt][kc][r] = *reinterpret_cast<uint32_t*>(&hh);
                    aPl[mt][kc][r] = *reinterpret_cast<uint32_t*>(&ll);
                }
            }
        }

#pragma unroll
        for (int kc = 0; kc < 4; kc++) {
#pragma unroll
            for (int dp = 0; dp < 4; dp++) {
                int row = kc * 16 + ((lane >> 3) & 1) * 8 + (lane & 7);
                int c16 = dp * 2 + (lane >> 4);
                uint32_t off = swz8(row, c16);
                uint32_t vh[4], vl[4];
                LDMATRIX_X4T(vh[0], vh[1], vh[2], vh[3], sk + 16384 + off);
                LDMATRIX_X4T(vl[0], vl[1], vl[2], vl[3], sk + 24576 + off);
#pragma unroll
                for (int mt = 0; mt < 2; mt++) {
                    MMA16816(acc[mt][2 * dp],     aPh[mt][kc], (vh + 0));
                    MMA16816(acc[mt][2 * dp + 1], aPh[mt][kc], (vh + 2));
                    MMA16816(acc[mt][2 * dp],     aPh[mt][kc], (vl + 0));
                    MMA16816(acc[mt][2 * dp + 1], aPh[mt][kc], (vl + 2));
                    MMA16816(acc[mt][2 * dp],     aPl[mt][kc], (vh + 0));
                    MMA16816(acc[mt][2 * dp + 1], aPl[mt][kc], (vh + 2));
                }
            }
        }
        __syncthreads();
    }

#pragma unroll
    for (int mt = 0; mt < 2; mt++) {
        float inv0 = 1.0f / lrow[mt][0];
        float inv1 = 1.0f / lrow[mt][1];
        int r0 = qbase + w * 32 + mt * 16 + (lane >> 2);
        size_t t0 = (size_t)(b * SEQ + r0) * DMODEL + h * HDIM;
        size_t t1 = t0 + 8 * DMODEL;
#pragma unroll
        for (int nt = 0; nt < 8; nt++) {
            int d = nt * 8 + (lane & 3) * 2;
            float v0 = acc[mt][nt][0] * inv0, v1 = acc[mt][nt][1] * inv0;
            float v2 = acc[mt][nt][2] * inv1, v3 = acc[mt][nt][3] * inv1;
            __nv_bfloat162 h01 = __floats2bfloat162_rn(v0, v1);
            __nv_bfloat162 h23 = __floats2bfloat162_rn(v2, v3);
            __nv_bfloat162 l01 = __floats2bfloat162_rn(
                v0 - __bfloat162float(h01.x), v1 - __bfloat162float(h01.y));
            __nv_bfloat162 l23 = __floats2bfloat162_rn(
                v2 - __bfloat162float(h23.x), v3 - __bfloat162float(h23.y));
            *reinterpret_cast<__nv_bfloat162*>(Oh + t0 + d) = h01;
            *reinterpret_cast<__nv_bfloat162*>(Oh + t1 + d) = h23;
            *reinterpret_cast<__nv_bfloat162*>(Ol + t0 + d) = l01;
            *reinterpret_cast<__nv_bfloat162*>(Ol + t1 + d) = l23;
        }
    }
}

// ---------------- launch ----------------------------------------------------
extern "C" void kernel_launch(void* const* d_in, const int* in_sizes, int n_in,
                              void* d_out, int out_size)
{
    const float* hidden = (const float*)d_in[0];
    const float* cs     = (const float*)d_in[1];
    const float* sn     = (const float*)d_in[2];
    const float* Wq     = (const float*)d_in[3];
    const float* Wk     = (const float*)d_in[4];
    const float* Wv     = (const float*)d_in[5];
    const float* Wo     = (const float*)d_in[6];
    float* out          = (float*)d_out;

    float* QKV = nullptr; cudaGetSymbolAddress((void**)&QKV, g_QKV);
    __nv_bfloat16* Ah = nullptr; cudaGetSymbolAddress((void**)&Ah, g_Ahi);
    __nv_bfloat16* Al = nullptr; cudaGetSymbolAddress((void**)&Al, g_Alo);
    __nv_bfloat16* Bh = nullptr; cudaGetSymbolAddress((void**)&Bh, g_Bhi);
    __nv_bfloat16* Bl = nullptr; cudaGetSymbolAddress((void**)&Bl, g_Blo);
    __nv_bfloat16* Qh = nullptr; cudaGetSymbolAddress((void**)&Qh, g_Qh);
    __nv_bfloat16* Ql = nullptr; cudaGetSymbolAddress((void**)&Ql, g_Ql);
    __nv_bfloat16* Kh = nullptr; cudaGetSymbolAddress((void**)&Kh, g_Kh);
    __nv_bfloat16* Kl = nullptr; cudaGetSymbolAddress((void**)&Kl, g_Kl);
    __nv_bfloat16* Vh = nullptr; cudaGetSymbolAddress((void**)&Vh, g_Vh);
    __nv_bfloat16* Vl = nullptr; cudaGetSymbolAddress((void**)&Vl, g_Vl);

    static bool attr_set = false;
    if (!attr_set) {
        cudaFuncSetAttribute(gemm_mma, cudaFuncAttributeMaxDynamicSharedMemorySize,
                             GEMM_SMEM);
        cudaFuncSetAttribute(flash_mma, cudaFuncAttributeMaxDynamicSharedMemorySize,
                             FLASH_SMEM);
        attr_set = true;
    }

    const int n4 = TOK * DMODEL / 4;

    split_kernel<<<n4 / 256, 256>>>(hidden, (__nv_bfloat162*)Ah,
                                    (__nv_bfloat162*)Al, n4);

    transpose_split<<<dim3(DMODEL / 32, DMODEL / 32), dim3(32, 8)>>>(Wq, Bh, Bl, DMODEL, 0);
    transpose_split<<<dim3(KVDIM / 32, DMODEL / 32), dim3(32, 8)>>>(Wk, Bh, Bl, KVDIM, DMODEL);
    transpose_split<<<dim3(KVDIM / 32, DMODEL / 32), dim3(32, 8)>>>(Wv, Bh, Bl, KVDIM, DMODEL + KVDIM);
    gemm_mma<<<dim3(QKVN / BN, TOK / BM), 256, GEMM_SMEM>>>(Ah, Al, Bh, Bl, QKV, QKVN);

    {
        int totq = TOK * NHEADS * 32;
        rope_split<<<(totq + 255) / 256, 256>>>(QKV, QKVN, 0, cs, sn, Qh, Ql,
                                                NHEADS, ATTN_SCALE);
        int totk = TOK * NKV * 32;
        rope_split<<<(totk + 255) / 256, 256>>>(QKV, QKVN, DMODEL, cs, sn, Kh, Kl,
                                                NKV, 1.0f);
        int nv = TOK * KVDIM / 4;
        split_strided<<<(nv + 255) / 256, 256>>>(QKV, QKVN, DMODEL + KVDIM,
                                                 (__nv_bfloat162*)Vh,
                                                 (__nv_bfloat162*)Vl, KVDIM);
    }

    transpose_split<<<dim3(DMODEL / 32, DMODEL / 32), dim3(32, 8)>>>(Wo, Bh, Bl, DMODEL, 0);

    {
        dim3 grid(SEQ / 128, NHEADS, BSZ);
        flash_mma<<<grid, 128, FLASH_SMEM>>>(Qh, Ql, Kh, Kl, Vh, Vl, Ah, Al);
    }

    gemm_mma<<<dim3(DMODEL / BN, TOK / BM), 256, GEMM_SMEM>>>(Ah, Al, Bh, Bl, out, DMODEL);
}

// round 13
// speedup vs baseline: 1.5238x; 1.0102x over previous
#include <cuda_runtime.h>
#include <cuda_bf16.h>
#include <cstdint>
#include <math_constants.h>

// Problem constants
#define BSZ 4
#define SEQ 1024
#define TOK (BSZ * SEQ)          // 4096
#define DMODEL 2048
#define NHEADS 32
#define NKV 8
#define HDIM 64
#define GROUPS (NHEADS / NKV)     // 4
#define KVDIM (NKV * HDIM)        // 512
#define QKVN (DMODEL + 2 * KVDIM) // 3072
#define ATTN_SCALE 0.125f

// ---------------- scratch (static device globals; no allocation) ----------
__device__ float g_QKV[(size_t)TOK * QKVN];
__device__ __align__(16) __nv_bfloat16 g_Ahi[(size_t)TOK * DMODEL];
__device__ __align__(16) __nv_bfloat16 g_Alo[(size_t)TOK * DMODEL];
__device__ __align__(16) __nv_bfloat16 g_Bhi[(size_t)QKVN * DMODEL]; // [N,K]
__device__ __align__(16) __nv_bfloat16 g_Blo[(size_t)QKVN * DMODEL];
__device__ __align__(16) __nv_bfloat16 g_Qh[(size_t)TOK * DMODEL];
__device__ __align__(16) __nv_bfloat16 g_Ql[(size_t)TOK * DMODEL];
__device__ __align__(16) __nv_bfloat16 g_Kh[(size_t)TOK * KVDIM];
__device__ __align__(16) __nv_bfloat16 g_Kl[(size_t)TOK * KVDIM];
__device__ __align__(16) __nv_bfloat16 g_Vh[(size_t)TOK * KVDIM];
__device__ __align__(16) __nv_bfloat16 g_Vl[(size_t)TOK * KVDIM];

// =================== PTX helpers (compute_103-safe) =========================
__device__ __forceinline__ uint32_t smem_u32(const void* p) {
    uint32_t a;
    asm("{ .reg .u64 t; cvta.to.shared.u64 t, %1; cvt.u32.u64 %0, t; }"
        : "=r"(a) : "l"(p));
    return a;
}

#define CP_ASYNC16(dst, src) \
    asm volatile("cp.async.cg.shared.global [%0], [%1], 16;" \
                 :: "r"(dst), "l"(src) : "memory")
#define CP_COMMIT() asm volatile("cp.async.commit_group;" ::: "memory")
#define CP_WAIT2()  asm volatile("cp.async.wait_group 2;" ::: "memory")
#define CP_WAIT1()  asm volatile("cp.async.wait_group 1;" ::: "memory")
#define CP_WAIT0()  asm volatile("cp.async.wait_group 0;" ::: "memory")

#define LDMATRIX_X4(r0, r1, r2, r3, addr) \
    asm volatile("ldmatrix.sync.aligned.m8n8.x4.shared.b16 {%0,%1,%2,%3}, [%4];" \
                 : "=r"(r0), "=r"(r1), "=r"(r2), "=r"(r3) : "r"(addr))

#define LDMATRIX_X4T(r0, r1, r2, r3, addr) \
    asm volatile("ldmatrix.sync.aligned.m8n8.x4.trans.shared.b16 {%0,%1,%2,%3}, [%4];" \
                 : "=r"(r0), "=r"(r1), "=r"(r2), "=r"(r3) : "r"(addr))

#define MMA16816(d, a, b) \
    asm volatile("mma.sync.aligned.m16n8k16.row.col.f32.bf16.bf16.f32 " \
                 "{%0,%1,%2,%3}, {%4,%5,%6,%7}, {%8,%9}, {%0,%1,%2,%3};" \
                 : "+f"((d)[0]), "+f"((d)[1]), "+f"((d)[2]), "+f"((d)[3]) \
                 : "r"((a)[0]), "r"((a)[1]), "r"((a)[2]), "r"((a)[3]), \
                   "r"((b)[0]), "r"((b)[1]))

// 128-byte rows, 8-chunk swizzle
__device__ __forceinline__ uint32_t swz8(int row, int c16) {
    return (uint32_t)(row * 128 + ((c16 ^ (row & 7)) * 16));
}

// =================== conversion kernels =====================================
__global__ void split_kernel(const float* __restrict__ A,
                             __nv_bfloat162* __restrict__ H,
                             __nv_bfloat162* __restrict__ L, int n4)
{
    int i = blockIdx.x * blockDim.x + threadIdx.x;
    if (i >= n4) return;
    float4 v = reinterpret_cast<const float4*>(A)[i];
    __nv_bfloat16 h0 = __float2bfloat16(v.x);
    __nv_bfloat16 h1 = __float2bfloat16(v.y);
    __nv_bfloat16 h2 = __float2bfloat16(v.z);
    __nv_bfloat16 h3 = __float2bfloat16(v.w);
    __nv_bfloat16 l0 = __float2bfloat16(v.x - __bfloat162float(h0));
    __nv_bfloat16 l1 = __float2bfloat16(v.y - __bfloat162float(h1));
    __nv_bfloat16 l2 = __float2bfloat16(v.z - __bfloat162float(h2));
    __nv_bfloat16 l3 = __float2bfloat16(v.w - __bfloat162float(h3));
    H[2 * i]     = __nv_bfloat162(h0, h1);
    H[2 * i + 1] = __nv_bfloat162(h2, h3);
    L[2 * i]     = __nv_bfloat162(l0, l1);
    L[2 * i + 1] = __nv_bfloat162(l2, l3);
}

// merged Wq/Wk/Wv transpose+split in ONE launch (region decode on blockIdx.x)
__global__ void transpose_split3(const float* __restrict__ Wq,
                                 const float* __restrict__ Wk,
                                 const float* __restrict__ Wv,
                                 __nv_bfloat16* __restrict__ Th,
                                 __nv_bfloat16* __restrict__ Tl)
{
    __shared__ float tile[32][33];
    int bx = blockIdx.x;
    const float* W;
    int N, rowoff;
    if (bx < 64)      { W = Wq; N = DMODEL; rowoff = 0; }
    else if (bx < 80) { W = Wk; N = KVDIM;  rowoff = DMODEL;        bx -= 64; }
    else              { W = Wv; N = KVDIM;  rowoff = DMODEL + KVDIM; bx -= 80; }

    int n = bx * 32 + threadIdx.x;
    int k = blockIdx.y * 32 + threadIdx.y;
#pragma unroll
    for (int j = 0; j < 32; j += 8)
        tile[threadIdx.y + j][threadIdx.x] = W[(size_t)(k + j) * N + n];
    __syncthreads();
    int k2 = blockIdx.y * 32 + threadIdx.x;
    int n2 = bx * 32 + threadIdx.y + rowoff;
#pragma unroll
    for (int j = 0; j < 32; j += 8) {
        float v = tile[threadIdx.x][threadIdx.y + j];
        __nv_bfloat16 h = __float2bfloat16(v);
        Th[(size_t)(n2 + j) * DMODEL + k2] = h;
        Tl[(size_t)(n2 + j) * DMODEL + k2] =
            __float2bfloat16(v - __bfloat162float(h));
    }
}

// single-launch transpose_split for Wo (same as verified version)
__global__ void transpose_split(const float* __restrict__ W,
                                __nv_bfloat16* __restrict__ Th,
                                __nv_bfloat16* __restrict__ Tl, int N, int rowoff)
{
    __shared__ float tile[32][33];
    int n = blockIdx.x * 32 + threadIdx.x;
    int k = blockIdx.y * 32 + threadIdx.y;
#pragma unroll
    for (int j = 0; j < 32; j += 8)
        tile[threadIdx.y + j][threadIdx.x] = W[(size_t)(k + j) * N + n];
    __syncthreads();
    int k2 = blockIdx.y * 32 + threadIdx.x;
    int n2 = blockIdx.x * 32 + threadIdx.y + rowoff;
#pragma unroll
    for (int j = 0; j < 32; j += 8) {
        float v = tile[threadIdx.x][threadIdx.y + j];
        __nv_bfloat16 h = __float2bfloat16(v);
        Th[(size_t)(n2 + j) * DMODEL + k2] = h;
        Tl[(size_t)(n2 + j) * DMODEL + k2] =
            __float2bfloat16(v - __bfloat162float(h));
    }
}

// merged QKV postprocess: Q rope, K rope, V split — ONE launch.
// Region decode on global index:
//   [0, TOK*1024)                : Q rope pairs  (32 heads * 32 pairs / token)
//   [TOK*1024, TOK*1280)         : K rope pairs  ( 8 heads * 32 pairs / token)
//   [TOK*1280, TOK*1408)         : V float4 split (512/4 = 128 / token)
#define QKVPP_TOTAL (TOK * 1408)
__global__ void qkv_post(const float* __restrict__ QKV,
                         const float* __restrict__ cs,
                         const float* __restrict__ sn,
                         __nv_bfloat16* __restrict__ Qh, __nv_bfloat16* __restrict__ Ql,
                         __nv_bfloat16* __restrict__ Kh, __nv_bfloat16* __restrict__ Kl,
                         __nv_bfloat162* __restrict__ Vh, __nv_bfloat162* __restrict__ Vl)
{
    int idx = blockIdx.x * blockDim.x + threadIdx.x;
    if (idx >= QKVPP_TOTAL) return;

    if (idx < TOK * 1024) {
        // Q rope: per-(token, head, pair)
        int i = idx & 31;
        int h = (idx >> 5) & 31;
        int t = idx >> 10;
        float c = cs[t * 32 + i];
        float s = sn[t * 32 + i];
        const float* in = QKV + (size_t)t * QKVN + h * HDIM;
        size_t ob = (size_t)t * DMODEL + h * HDIM;
        float x1 = in[i], x2 = in[i + 32];
        float y1 = (x1 * c - x2 * s) * ATTN_SCALE;
        float y2 = (x2 * c + x1 * s) * ATTN_SCALE;
        __nv_bfloat16 h1 = __float2bfloat16(y1);
        __nv_bfloat16 h2 = __float2bfloat16(y2);
        Qh[ob + i]      = h1;
        Qh[ob + i + 32] = h2;
        Ql[ob + i]      = __float2bfloat16(y1 - __bfloat162float(h1));
        Ql[ob + i + 32] = __float2bfloat16(y2 - __bfloat162float(h2));
    } else if (idx < TOK * 1280) {
        // K rope
        int r = idx - TOK * 1024;
        int i = r & 31;
        int h = (r >> 5) & 7;
        int t = r >> 8;
        float c = cs[t * 32 + i];
        float s = sn[t * 32 + i];
        const float* in = QKV + (size_t)t * QKVN + DMODEL + h * HDIM;
        size_t ob = (size_t)t * KVDIM + h * HDIM;
        float x1 = in[i], x2 = in[i + 32];
        float y1 = x1 * c - x2 * s;
        float y2 = x2 * c + x1 * s;
        __nv_bfloat16 h1 = __float2bfloat16(y1);
        __nv_bfloat16 h2 = __float2bfloat16(y2);
        Kh[ob + i]      = h1;
        Kh[ob + i + 32] = h2;
        Kl[ob + i]      = __float2bfloat16(y1 - __bfloat162float(h1));
        Kl[ob + i + 32] = __float2bfloat16(y2 - __bfloat162float(h2));
    } else {
        // V split (float4 granules)
        int r = idx - TOK * 1280;
        int c = r & 127;
        int t = r >> 7;
        float4 v = *reinterpret_cast<const float4*>(
            QKV + (size_t)t * QKVN + DMODEL + KVDIM + c * 4);
        __nv_bfloat16 h0 = __float2bfloat16(v.x);
        __nv_bfloat16 h1 = __float2bfloat16(v.y);
        __nv_bfloat16 h2 = __float2bfloat16(v.z);
        __nv_bfloat16 h3 = __float2bfloat16(v.w);
        size_t o = ((size_t)t * KVDIM + c * 4) / 2;
        Vh[o]     = __nv_bfloat162(h0, h1);
        Vh[o + 1] = __nv_bfloat162(h2, h3);
        Vl[o]     = __nv_bfloat162(__float2bfloat16(v.x - __bfloat162float(h0)),
                                   __float2bfloat16(v.y - __bfloat162float(h1)));
        Vl[o + 1] = __nv_bfloat162(__float2bfloat16(v.z - __bfloat162float(h2)),
                                   __float2bfloat16(v.w - __bfloat162float(h3)));
    }
}

// =================== HMMA GEMM (verified R8/R12 mainloop) ===================
#define BM 128
#define BN 128
#define BK 64
#define TILE_B (128 * BK * 2)          // 16384
#define STAGE_B (4 * TILE_B)           // 65536
#define GEMM_SMEM (3 * STAGE_B)        // 196608

__device__ __forceinline__ void stage_load(
    const __nv_bfloat16* __restrict__ aH, const __nv_bfloat16* __restrict__ aL,
    const __nv_bfloat16* __restrict__ bH, const __nv_bfloat16* __restrict__ bL,
    uint32_t sbase, int k0, int tid)
{
#pragma unroll
    for (int j = 0; j < 4; j++) {
        int i = tid + j * 256;
        int row = i >> 3;
        int c16 = i & 7;
        uint32_t doff = swz8(row, c16);
        size_t goff = (size_t)row * DMODEL + k0 + c16 * 8;
        CP_ASYNC16(sbase + 0 * TILE_B + doff, aH + goff);
        CP_ASYNC16(sbase + 1 * TILE_B + doff, aL + goff);
        CP_ASYNC16(sbase + 2 * TILE_B + doff, bH + goff);
        CP_ASYNC16(sbase + 3 * TILE_B + doff, bL + goff);
    }
}

__global__ void __launch_bounds__(256, 1) gemm_mma(
    const __nv_bfloat16* __restrict__ Ahi, const __nv_bfloat16* __restrict__ Alo,
    const __nv_bfloat16* __restrict__ Bhi, const __nv_bfloat16* __restrict__ Blo,
    float* __restrict__ C, int N)
{
    extern __shared__ char smem[];
    uint32_t sb = smem_u32(smem);
    const int tid = threadIdx.x;
    const int lane = tid & 31;
    const int wid = tid >> 5;
    const int wm = wid >> 2;
    const int wn = wid & 3;
    const int brow = blockIdx.y * BM;
    const int bcol = blockIdx.x * BN;

    const __nv_bfloat16* aH = Ahi + (size_t)brow * DMODEL;
    const __nv_bfloat16* aL = Alo + (size_t)brow * DMODEL;
    const __nv_bfloat16* bH = Bhi + (size_t)bcol * DMODEL;
    const __nv_bfloat16* bL = Blo + (size_t)bcol * DMODEL;

    float acc[4][4][4];
#pragma unroll
    for (int i = 0; i < 4; i++)
#pragma unroll
        for (int j = 0; j < 4; j++)
#pragma unroll
            for (int q = 0; q < 4; q++) acc[i][j][q] = 0.f;

    const int NC = DMODEL / BK;   // 32
#pragma unroll
    for (int s = 0; s < 3; s++) {
        stage_load(aH, aL, bH, bL, sb + s * STAGE_B, s * BK, tid);
        CP_COMMIT();
    }

    for (int c = 0; c < NC; c++) {
        if (c + 2 < NC)      CP_WAIT2();
        else if (c + 1 < NC) CP_WAIT1();
        else                 CP_WAIT0();
        __syncthreads();

        uint32_t st = sb + (uint32_t)(c % 3) * STAGE_B;

#pragma unroll
        for (int ks = 0; ks < 4; ks++) {
            uint32_t fAh[4][4], fAl[4][4];
#pragma unroll
            for (int mt = 0; mt < 4; mt++) {
                int row = wm * 64 + mt * 16 + (lane & 15);
                int c16 = ks * 2 + (lane >> 4);
                uint32_t off = swz8(row, c16);
                LDMATRIX_X4(fAh[mt][0], fAh[mt][1], fAh[mt][2], fAh[mt][3],
                            st + 0 * TILE_B + off);
                LDMATRIX_X4(fAl[mt][0], fAl[mt][1], fAl[mt][2], fAl[mt][3],
                            st + 1 * TILE_B + off);
            }
            uint32_t fBh[4][2], fBl[4][2];
#pragma unroll
            for (int pr = 0; pr < 2; pr++) {
                int nrel = wn * 32 + pr * 16 + ((lane >> 4) * 8 + (lane & 7));
                int c16 = ks * 2 + ((lane >> 3) & 1);
                uint32_t off = swz8(nrel, c16);
                LDMATRIX_X4(fBh[2 * pr][0], fBh[2 * pr][1],
                            fBh[2 * pr + 1][0], fBh[2 * pr + 1][1],
                            st + 2 * TILE_B + off);
                LDMATRIX_X4(fBl[2 * pr][0], fBl[2 * pr][1],
                            fBl[2 * pr + 1][0], fBl[2 * pr + 1][1],
                            st + 3 * TILE_B + off);
            }
#pragma unroll
            for (int mt = 0; mt < 4; mt++)
#pragma unroll
                for (int nt = 0; nt < 4; nt++) {
                    MMA16816(acc[mt][nt], fAh[mt], fBh[nt]);
                    MMA16816(acc[mt][nt], fAh[mt], fBl[nt]);
                    MMA16816(acc[mt][nt], fAl[mt], fBh[nt]);
                }
        }
        __syncthreads();
        if (c + 3 < NC) {
            stage_load(aH, aL, bH, bL, st, (c + 3) * BK, tid);
            CP_COMMIT();
        }
    }

#pragma unroll
    for (int mt = 0; mt < 4; mt++) {
#pragma unroll
        for (int nt = 0; nt < 4; nt++) {
            int m = brow + wm * 64 + mt * 16 + (lane >> 2);
            int n = bcol + wn * 32 + nt * 8 + (lane & 3) * 2;
            float2 v0 = make_float2(acc[mt][nt][0], acc[mt][nt][1]);
            float2 v1 = make_float2(acc[mt][nt][2], acc[mt][nt][3]);
            *reinterpret_cast<float2*>(C + (size_t)m * N + n) = v0;
            *reinterpret_cast<float2*>(C + (size_t)(m + 8) * N + n) = v1;
        }
    }
}

// =================== tensor-core flash attention (verified R8 + LPT) ========
#define FQ_SMEM 32768
#define KV_BUF  32768
#define FLASH_SMEM (FQ_SMEM + 2 * KV_BUF)

__device__ __forceinline__ void stage_kv(
    const __nv_bfloat16* __restrict__ Kh, const __nv_bfloat16* __restrict__ Kl,
    const __nv_bfloat16* __restrict__ Vh, const __nv_bfloat16* __restrict__ Vl,
    uint32_t sbase, size_t gbase, int tid)
{
#pragma unroll
    for (int t = 0; t < 4; t++) {
        int i = tid + t * 128;
        int row = i >> 3;
        int c16 = i & 7;
        uint32_t doff = swz8(row, c16);
        size_t goff = gbase + (size_t)row * KVDIM + c16 * 8;
        CP_ASYNC16(sbase + 0     + doff, Kh + goff);
        CP_ASYNC16(sbase + 8192  + doff, Kl + goff);
        CP_ASYNC16(sbase + 16384 + doff, Vh + goff);
        CP_ASYNC16(sbase + 24576 + doff, Vl + goff);
    }
}

__global__ void __launch_bounds__(128) flash_mma(
    const __nv_bfloat16* __restrict__ Qh, const __nv_bfloat16* __restrict__ Ql,
    const __nv_bfloat16* __restrict__ Kh, const __nv_bfloat16* __restrict__ Kl,
    const __nv_bfloat16* __restrict__ Vh, const __nv_bfloat16* __restrict__ Vl,
    __nv_bfloat16* __restrict__ Oh, __nv_bfloat16* __restrict__ Ol)
{
    extern __shared__ char smem[];
    uint32_t sb = smem_u32(smem);
    // LPT: longest CTAs (largest qt) scheduled first
    const int qt = (int)gridDim.x - 1 - (int)blockIdx.x;
    const int h  = blockIdx.y;
    const int b  = blockIdx.z;
    const int kvh = h / GROUPS;
    const int tid = threadIdx.x;
    const int lane = tid & 31;
    const int w = tid >> 5;
    const int qbase = qt * 128;

#pragma unroll
    for (int t = 0; t < 8; t++) {
        int i = tid + t * 128;
        int row = i >> 3;
        int c16 = i & 7;
        uint32_t doff = swz8(row, c16);
        size_t goff = (size_t)(b * SEQ + qbase + row) * DMODEL + h * HDIM + c16 * 8;
        CP_ASYNC16(sb + doff, Qh + goff);
        CP_ASYNC16(sb + 16384 + doff, Ql + goff);
    }
    size_t kvg0 = (size_t)(b * SEQ) * KVDIM + kvh * HDIM;
    stage_kv(Kh, Kl, Vh, Vl, sb + FQ_SMEM, kvg0, tid);
    CP_COMMIT();

    float acc[2][8][4];
#pragma unroll
    for (int mt = 0; mt < 2; mt++)
#pragma unroll
        for (int nt = 0; nt < 8; nt++)
#pragma unroll
            for (int e = 0; e < 4; e++) acc[mt][nt][e] = 0.f;
    float mrow[2][2] = {{-CUDART_INF_F, -CUDART_INF_F},
                        {-CUDART_INF_F, -CUDART_INF_F}};
    float lrow[2][2] = {{0.f, 0.f}, {0.f, 0.f}};

    const int nb = 2 * qt + 2;
    for (int c = 0; c < nb; c++) {
        if (c + 1 < nb) {
            stage_kv(Kh, Kl, Vh, Vl, sb + FQ_SMEM + ((c + 1) & 1) * KV_BUF,
                     kvg0 + (size_t)(c + 1) * 64 * KVDIM, tid);
            CP_COMMIT();
            CP_WAIT1();
        } else {
            CP_WAIT0();
        }
        __syncthreads();

        uint32_t sk = sb + FQ_SMEM + (c & 1) * KV_BUF;

        float S[2][8][4];
#pragma unroll
        for (int mt = 0; mt < 2; mt++)
#pragma unroll
            for (int nt = 0; nt < 8; nt++)
#pragma unroll
                for (int e = 0; e < 4; e++) S[mt][nt][e] = 0.f;

#pragma unroll
        for (int ks = 0; ks < 4; ks++) {
            uint32_t qh[2][4], ql[2][4];
#pragma unroll
            for (int mt = 0; mt < 2; mt++) {
                int row = w * 32 + mt * 16 + (lane & 15);
                int c16 = ks * 2 + (lane >> 4);
                uint32_t off = swz8(row, c16);
                LDMATRIX_X4(qh[mt][0], qh[mt][1], qh[mt][2], qh[mt][3], sb + off);
                LDMATRIX_X4(ql[mt][0], ql[mt][1], ql[mt][2], ql[mt][3],
                            sb + 16384 + off);
            }
#pragma unroll
            for (int np = 0; np < 4; np++) {
                int row = np * 16 + ((lane >> 4) * 8) + (lane & 7);
                int c16 = ks * 2 + ((lane >> 3) & 1);
                uint32_t off = swz8(row, c16);
                uint32_t kh[4], kl[4];
                LDMATRIX_X4(kh[0], kh[1], kh[2], kh[3], sk + off);
                LDMATRIX_X4(kl[0], kl[1], kl[2], kl[3], sk + 8192 + off);
#pragma unroll
                for (int mt = 0; mt < 2; mt++) {
                    MMA16816(S[mt][2 * np],     qh[mt], (kh + 0));
                    MMA16816(S[mt][2 * np + 1], qh[mt], (kh + 2));
                    MMA16816(S[mt][2 * np],     qh[mt], (kl + 0));
                    MMA16816(S[mt][2 * np + 1], qh[mt], (kl + 2));
                    MMA16816(S[mt][2 * np],     ql[mt], (kh + 0));
                    MMA16816(S[mt][2 * np + 1], ql[mt], (kh + 2));
                }
            }
        }

        if (c >= 2 * qt) {
            int kb = c * 64;
#pragma unroll
            for (int mt = 0; mt < 2; mt++) {
                int r0 = qbase + w * 32 + mt * 16 + (lane >> 2);
#pragma unroll
                for (int nt = 0; nt < 8; nt++) {
                    int key = kb + nt * 8 + (lane & 3) * 2;
                    if (key > r0)     S[mt][nt][0] = -CUDART_INF_F;
                    if (key + 1 > r0) S[mt][nt][1] = -CUDART_INF_F;
                    if (key > r0 + 8)     S[mt][nt][2] = -CUDART_INF_F;
                    if (key + 1 > r0 + 8) S[mt][nt][3] = -CUDART_INF_F;
                }
            }
        }

        uint32_t aPh[2][4][4], aPl[2][4][4];
#pragma unroll
        for (int mt = 0; mt < 2; mt++) {
#pragma unroll
            for (int e2 = 0; e2 < 2; e2++) {
                float mx = -CUDART_INF_F;
#pragma unroll
                for (int nt = 0; nt < 8; nt++)
                    mx = fmaxf(mx, fmaxf(S[mt][nt][2 * e2], S[mt][nt][2 * e2 + 1]));
                mx = fmaxf(mx, __shfl_xor_sync(0xffffffffu, mx, 1));
                mx = fmaxf(mx, __shfl_xor_sync(0xffffffffu, mx, 2));
                float mn = fmaxf(mrow[mt][e2], mx);
                float alpha = __expf(mrow[mt][e2] - mn);
                mrow[mt][e2] = mn;
                float sum = 0.f;
#pragma unroll
                for (int nt = 0; nt < 8; nt++) {
                    float p0 = __expf(S[mt][nt][2 * e2] - mn);
                    float p1 = __expf(S[mt][nt][2 * e2 + 1] - mn);
                    S[mt][nt][2 * e2] = p0;
                    S[mt][nt][2 * e2 + 1] = p1;
                    sum += p0 + p1;
                }
                sum += __shfl_xor_sync(0xffffffffu, sum, 1);
                sum += __shfl_xor_sync(0xffffffffu, sum, 2);
                lrow[mt][e2] = lrow[mt][e2] * alpha + sum;
#pragma unroll
                for (int nt = 0; nt < 8; nt++) {
                    acc[mt][nt][2 * e2] *= alpha;
                    acc[mt][nt][2 * e2 + 1] *= alpha;
                }
            }
#pragma unroll
            for (int kc = 0; kc < 4; kc++) {
#pragma unroll
                for (int r = 0; r < 4; r++) {
                    int nt = 2 * kc + (r >> 1);
                    int e0 = (r & 1) * 2;
                    float p0 = S[mt][nt][e0], p1 = S[mt][nt][e0 + 1];
                    __nv_bfloat162 hh = __floats2bfloat162_rn(p0, p1);
                    float r0 = p0 - __bfloat162float(hh.x);
                    float r1 = p1 - __bfloat162float(hh.y);
                    __nv_bfloat162 ll = __floats2bfloat162_rn(r0, r1);
                    aPh[mt][kc][r] = *reinterpret_cast<uint32_t*>(&hh);
                    aPl[mt][kc][r] = *reinterpret_cast<uint32_t*>(&ll);
                }
            }
        }

#pragma unroll
        for (int kc = 0; kc < 4; kc++) {
#pragma unroll
            for (int dp = 0; dp < 4; dp++) {
                int row = kc * 16 + ((lane >> 3) & 1) * 8 + (lane & 7);
                int c16 = dp * 2 + (lane >> 4);
                uint32_t off = swz8(row, c16);
                uint32_t vh[4], vl[4];
                LDMATRIX_X4T(vh[0], vh[1], vh[2], vh[3], sk + 16384 + off);
                LDMATRIX_X4T(vl[0], vl[1], vl[2], vl[3], sk + 24576 + off);
#pragma unroll
                for (int mt = 0; mt < 2; mt++) {
                    MMA16816(acc[mt][2 * dp],     aPh[mt][kc], (vh + 0));
                    MMA16816(acc[mt][2 * dp + 1], aPh[mt][kc], (vh + 2));
                    MMA16816(acc[mt][2 * dp],     aPh[mt][kc], (vl + 0));
                    MMA16816(acc[mt][2 * dp + 1], aPh[mt][kc], (vl + 2));
                    MMA16816(acc[mt][2 * dp],     aPl[mt][kc], (vh + 0));
                    MMA16816(acc[mt][2 * dp + 1], aPl[mt][kc], (vh + 2));
                }
            }
        }
        __syncthreads();
    }

#pragma unroll
    for (int mt = 0; mt < 2; mt++) {
        float inv0 = 1.0f / lrow[mt][0];
        float inv1 = 1.0f / lrow[mt][1];
        int r0 = qbase + w * 32 + mt * 16 + (lane >> 2);
        size_t t0 = (size_t)(b * SEQ + r0) * DMODEL + h * HDIM;
        size_t t1 = t0 + 8 * DMODEL;
#pragma unroll
        for (int nt = 0; nt < 8; nt++) {
            int d = nt * 8 + (lane & 3) * 2;
            float v0 = acc[mt][nt][0] * inv0, v1 = acc[mt][nt][1] * inv0;
            float v2 = acc[mt][nt][2] * inv1, v3 = acc[mt][nt][3] * inv1;
            __nv_bfloat162 h01 = __floats2bfloat162_rn(v0, v1);
            __nv_bfloat162 h23 = __floats2bfloat162_rn(v2, v3);
            __nv_bfloat162 l01 = __floats2bfloat162_rn(
                v0 - __bfloat162float(h01.x), v1 - __bfloat162float(h01.y));
            __nv_bfloat162 l23 = __floats2bfloat162_rn(
                v2 - __bfloat162float(h23.x), v3 - __bfloat162float(h23.y));
            *reinterpret_cast<__nv_bfloat162*>(Oh + t0 + d) = h01;
            *reinterpret_cast<__nv_bfloat162*>(Oh + t1 + d) = h23;
            *reinterpret_cast<__nv_bfloat162*>(Ol + t0 + d) = l01;
            *reinterpret_cast<__nv_bfloat162*>(Ol + t1 + d) = l23;
        }
    }
}

// ---------------- launch ----------------------------------------------------
extern "C" void kernel_launch(void* const* d_in, const int* in_sizes, int n_in,
                              void* d_out, int out_size)
{
    const float* hidden = (const float*)d_in[0];
    const float* cs     = (const float*)d_in[1];
    const float* sn     = (const float*)d_in[2];
    const float* Wq     = (const float*)d_in[3];
    const float* Wk     = (const float*)d_in[4];
    const float* Wv     = (const float*)d_in[5];
    const float* Wo     = (const float*)d_in[6];
    float* out          = (float*)d_out;

    float* QKV = nullptr; cudaGetSymbolAddress((void**)&QKV, g_QKV);
    __nv_bfloat16* Ah = nullptr; cudaGetSymbolAddress((void**)&Ah, g_Ahi);
    __nv_bfloat16* Al = nullptr; cudaGetSymbolAddress((void**)&Al, g_Alo);
    __nv_bfloat16* Bh = nullptr; cudaGetSymbolAddress((void**)&Bh, g_Bhi);
    __nv_bfloat16* Bl = nullptr; cudaGetSymbolAddress((void**)&Bl, g_Blo);
    __nv_bfloat16* Qh = nullptr; cudaGetSymbolAddress((void**)&Qh, g_Qh);
    __nv_bfloat16* Ql = nullptr; cudaGetSymbolAddress((void**)&Ql, g_Ql);
    __nv_bfloat16* Kh = nullptr; cudaGetSymbolAddress((void**)&Kh, g_Kh);
    __nv_bfloat16* Kl = nullptr; cudaGetSymbolAddress((void**)&Kl, g_Kl);
    __nv_bfloat16* Vh = nullptr; cudaGetSymbolAddress((void**)&Vh, g_Vh);
    __nv_bfloat16* Vl = nullptr; cudaGetSymbolAddress((void**)&Vl, g_Vl);

    static bool attr_set = false;
    if (!attr_set) {
        cudaFuncSetAttribute(gemm_mma, cudaFuncAttributeMaxDynamicSharedMemorySize,
                             GEMM_SMEM);
        cudaFuncSetAttribute(flash_mma, cudaFuncAttributeMaxDynamicSharedMemorySize,
                             FLASH_SMEM);
        attr_set = true;
    }

    const int n4 = TOK * DMODEL / 4;

    // hidden -> bf16 hi/lo (A operand)
    split_kernel<<<n4 / 256, 256>>>(hidden, (__nv_bfloat162*)Ah,
                                    (__nv_bfloat162*)Al, n4);

    // B = [WqT ; WkT ; WvT] in ONE launch
    transpose_split3<<<dim3(96, DMODEL / 32), dim3(32, 8)>>>(Wq, Wk, Wv, Bh, Bl);

    // fused QKV GEMM
    gemm_mma<<<dim3(QKVN / BN, TOK / BM), 256, GEMM_SMEM>>>(Ah, Al, Bh, Bl, QKV, QKVN);

    // merged postprocess: Q rope + K rope + V split, ONE launch
    qkv_post<<<(QKVPP_TOTAL + 255) / 256, 256>>>(QKV, cs, sn, Qh, Ql, Kh, Kl,
                                                 (__nv_bfloat162*)Vh,
                                                 (__nv_bfloat162*)Vl);

    // Wo transpose (Bh/Bl free after QKV GEMM)
    transpose_split<<<dim3(DMODEL / 32, DMODEL / 32), dim3(32, 8)>>>(Wo, Bh, Bl, DMODEL, 0);

    // flash attention (LPT-ordered) -> writes bf16 hi/lo into Wo-GEMM A buffers
    {
        dim3 grid(SEQ / 128, NHEADS, BSZ);
        flash_mma<<<grid, 128, FLASH_SMEM>>>(Qh, Ql, Kh, Kl, Vh, Vl, Ah, Al);
    }

    // out = attn @ Wo
    gemm_mma<<<dim3(DMODEL / BN, TOK / BM), 256, GEMM_SMEM>>>(Ah, Al, Bh, Bl, out, DMODEL);
}